// round 13
// baseline (speedup 1.0000x reference)
#include <cuda_runtime.h>
#include <cstdint>

// SimplifiedEncoder: 2-layer weight-shared LSTM, SEQ=512, B=128, D=1024.
// ONE persistent kernel (single graph node -> no graph-upload leak).
// Per cell: C[128 x 4096] = A[128 x 2048] @ Wcat^T, split-K=8 across CTAs:
//   grid 128 = 16 n_tiles (256 gate-rows) x 8 k_splits (256 K).
//   GEMM phase writes fp32 partials to g_P; barrier; reduction+LSTM epilogue
//   (CTA = batch row, coalesced); barrier. mma.sync m16n8k8 tf32 (rna cvt),
//   cp.async double-buffered smem pipeline. Software grid barrier with
//   replay-safe monotonic generation.

#define BATCH  128
#define DIM    1024
#define BD     (BATCH * DIM)
#define SEQL   512
#define NCTA   128
#define NTHR   256
#define KC     32
#define NSTG   8          // 256 K per split / KC
#define LDS_S  36         // smem row stride (floats): (36r+c)%32 = (4r+c)%32 -> conflict-free

// ---- persistent state (fp32) ----
__device__ float g_h [BD];
__device__ float g_c [BD];
__device__ float g_h2[BD];
__device__ float g_c2[BD];
__device__ float g_h1[BD];
__device__ float g_c1[BD];
__device__ float g_bias[4 * DIM];            // b_ih + b_hh
__device__ float g_P[8][BATCH][4 * DIM];     // split-K partials, 16 MB
__device__ unsigned g_barGen = 0;            // monotonic across replays
__device__ unsigned g_barCnt = 0;

// ---- helpers ----
__device__ __forceinline__ void cp16(float* sdst, const float* gsrc) {
    unsigned s = (unsigned)__cvta_generic_to_shared(sdst);
    asm volatile("cp.async.cg.shared.global [%0], [%1], 16;\n" :: "r"(s), "l"(gsrc));
}
__device__ __forceinline__ void cp_commit() { asm volatile("cp.async.commit_group;\n"); }
__device__ __forceinline__ void cp_wait1()  { asm volatile("cp.async.wait_group 1;\n" ::: "memory"); }
__device__ __forceinline__ void cp_wait0()  { asm volatile("cp.async.wait_group 0;\n" ::: "memory"); }

__device__ __forceinline__ uint32_t tf32r(float v) {
    uint32_t r; asm("cvt.rna.tf32.f32 %0, %1;" : "=r"(r) : "f"(v)); return r;
}
__device__ __forceinline__ void mma8(float* d, const uint32_t* a, uint32_t b0, uint32_t b1) {
    asm volatile(
        "mma.sync.aligned.m16n8k8.row.col.f32.tf32.tf32.f32 "
        "{%0,%1,%2,%3}, {%4,%5,%6,%7}, {%8,%9}, {%0,%1,%2,%3};\n"
        : "+f"(d[0]), "+f"(d[1]), "+f"(d[2]), "+f"(d[3])
        : "r"(a[0]), "r"(a[1]), "r"(a[2]), "r"(a[3]), "r"(b0), "r"(b1));
}
__device__ __forceinline__ float sigf(float x)   { return __fdividef(1.0f, 1.0f + __expf(-x)); }
__device__ __forceinline__ float tanh_f(float x) { return __fmaf_rn(2.0f, sigf(2.0f * x), -1.0f); }

// Grid barrier. target = entry_gen + call_index (monotonic; replay-safe since
// g_barGen persists and each launch reads its own base before any arrival).
__device__ __forceinline__ void gridbar(unsigned target) {
    __syncthreads();
    if (threadIdx.x == 0) {
        __threadfence();
        if (atomicAdd(&g_barCnt, 1u) == NCTA - 1u) {
            g_barCnt = 0u;
            __threadfence();
            atomicExch(&g_barGen, target);
        } else {
            while ((int)(atomicAdd(&g_barGen, 0u) - target) < 0) __nanosleep(64);
        }
        __threadfence();
    }
    __syncthreads();
}

// ---- GEMM phase: partial [128 x 256] over a 256-wide K slice ----
// LAYER 1: A = [emb[x_t] | h ],  LAYER 2: A = [h1 | h2].  splits 0-3 = first
// half (Wih), 4-7 = second half (Whh); each split is source-pure.
template<int LAYER>
__device__ void gemm_phase(float* As, float* Ws, const float** Abase,
                           const int* __restrict__ xt,
                           const float* __restrict__ emb,
                           const float* __restrict__ Wih,
                           const float* __restrict__ Whh)
{
    const int tid = threadIdx.x;
    const int nt  = blockIdx.x & 15;
    const int ks  = blockIdx.x >> 4;
    const int n0  = nt * 256;
    const bool hi = (ks >= 4);
    const int koff = (ks & 3) * 256;

    if (tid < BATCH) {
        const float* b;
        if (LAYER == 1) b = hi ? (g_h  + tid * DIM + koff)
                               : (emb + (size_t)xt[tid] * DIM + koff);
        else            b = hi ? (g_h2 + tid * DIM + koff)
                               : (g_h1 + tid * DIM + koff);
        Abase[tid] = b;
    }
    const float* Wb0 = (hi ? Whh : Wih) + (size_t)n0 * DIM + koff;
    __syncthreads();

    float acc[4][8][4];
    #pragma unroll
    for (int qm = 0; qm < 4; qm++)
        #pragma unroll
        for (int qn = 0; qn < 8; qn++)
            #pragma unroll
            for (int p = 0; p < 4; p++) acc[qm][qn][p] = 0.0f;

    const int pr  = tid >> 3;          // base row for cp.async (rows pr + i*32)
    const int pc4 = (tid & 7) * 4;     // float offset of this thread's 16B chunk

    auto prefetch = [&](int s) {
        float* ad = As + (s & 1) * (128 * LDS_S);
        float* wd = Ws + (s & 1) * (256 * LDS_S);
        const int kc = s * KC;
        #pragma unroll
        for (int i = 0; i < 4; i++) {
            int r = pr + i * 32;
            cp16(ad + r * LDS_S + pc4, Abase[r] + kc + pc4);
        }
        #pragma unroll
        for (int i = 0; i < 8; i++) {
            int r = pr + i * 32;
            cp16(wd + r * LDS_S + pc4, Wb0 + (size_t)r * DIM + kc + pc4);
        }
        cp_commit();
    };

    const int lane = tid & 31, warp = tid >> 5;
    const int grp  = lane >> 2, tig = lane & 3;
    const int mb   = (warp >> 2) * 64;   // warp M offset (2 warps in M)
    const int nb   = (warp & 3) * 64;    // warp N offset (4 warps in N)

    auto docompute = [&](int s) {
        const float* Ab  = As + (s & 1) * (128 * LDS_S);
        const float* Wsb = Ws + (s & 1) * (256 * LDS_S);
        #pragma unroll
        for (int k8 = 0; k8 < KC / 8; k8++) {
            const int kk = k8 * 8;
            uint32_t af[4][4];
            #pragma unroll
            for (int qm = 0; qm < 4; qm++) {
                const float* p = Ab + (mb + qm * 16 + grp) * LDS_S + kk + tig;
                af[qm][0] = tf32r(p[0]);
                af[qm][1] = tf32r(p[8 * LDS_S]);
                af[qm][2] = tf32r(p[4]);
                af[qm][3] = tf32r(p[8 * LDS_S + 4]);
            }
            uint32_t bf[8][2];
            #pragma unroll
            for (int qn = 0; qn < 8; qn++) {
                const float* p = Wsb + (nb + qn * 8 + grp) * LDS_S + kk + tig;
                bf[qn][0] = tf32r(p[0]);
                bf[qn][1] = tf32r(p[4]);
            }
            #pragma unroll
            for (int qm = 0; qm < 4; qm++)
                #pragma unroll
                for (int qn = 0; qn < 8; qn++)
                    mma8(acc[qm][qn], af[qm], bf[qn][0], bf[qn][1]);
        }
    };

    prefetch(0);
    #pragma unroll 1
    for (int s = 0; s < NSTG; s++) {
        if (s + 1 < NSTG) { prefetch(s + 1); cp_wait1(); }
        else              { cp_wait0(); }
        __syncthreads();
        docompute(s);
        __syncthreads();
    }

    // store partials (float2: adjacent n-cols per C-frag pair)
    float* Pks = &g_P[ks][0][0];
    #pragma unroll
    for (int qm = 0; qm < 4; qm++) {
        #pragma unroll
        for (int qn = 0; qn < 8; qn++) {
            const int b0  = mb + qm * 16 + grp;
            const int col = n0 + nb + qn * 8 + 2 * tig;
            *(float2*)(Pks + (size_t)b0 * 4096 + col) =
                make_float2(acc[qm][qn][0], acc[qm][qn][1]);
            *(float2*)(Pks + (size_t)(b0 + 8) * 4096 + col) =
                make_float2(acc[qm][qn][2], acc[qm][qn][3]);
        }
    }
}

// ---- reduction + LSTM epilogue. CTA = batch row b; threads sweep j. ----
template<int LAYER>
__device__ void epi_phase(const int* __restrict__ xt)
{
    const int b = blockIdx.x;
    const bool pad = (xt[b] == 0);
    #pragma unroll
    for (int q = 0; q < 4; q++) {
        const int j = q * NTHR + threadIdx.x;      // 0..1023
        float s[4];
        #pragma unroll
        for (int g = 0; g < 4; g++) {
            float a = g_bias[g * DIM + j];
            #pragma unroll
            for (int sp = 0; sp < 8; sp++)
                a += g_P[sp][b][g * DIM + j];
            s[g] = a;
        }
        const int idx = b * DIM + j;
        const float ig = sigf(s[0]);
        const float fg = sigf(s[1]);
        const float gg = tanh_f(s[2]);
        const float og = sigf(s[3]);
        if (LAYER == 1) {
            const float cn = fg * g_c[idx] + ig * gg;
            g_c1[idx] = cn;
            g_h1[idx] = og * tanh_f(cn);
        } else {
            const float c2n = fg * g_c2[idx] + ig * gg;
            const float h2n = og * tanh_f(c2n);
            const float hold = g_h[idx];
            const float cold = g_c[idx];
            // faithful to reference: layer-2 pads fall back to layer-1 PRE-step state
            g_h [idx] = pad ? hold : g_h1[idx];
            g_c [idx] = pad ? cold : g_c1[idx];
            g_h2[idx] = pad ? hold : h2n;
            g_c2[idx] = pad ? cold : c2n;
        }
    }
}

// ---- the single persistent kernel ----
__global__ void __launch_bounds__(NTHR, 1)
lstm_persist(const int*   __restrict__ x,
             const float* __restrict__ emb,
             const float* __restrict__ Wih,
             const float* __restrict__ Whh,
             const float* __restrict__ bih,
             const float* __restrict__ bhh,
             const float* __restrict__ h0,
             const float* __restrict__ c0,
             const float* __restrict__ h02,
             const float* __restrict__ c02,
             float* __restrict__ out)
{
    extern __shared__ float smf[];
    float* As = smf;                                   // [2][128*36]
    float* Ws = smf + 2 * 128 * LDS_S;                 // [2][256*36]
    const float** Abase = (const float**)(smf + 2 * 128 * LDS_S + 2 * 256 * LDS_S);
    __shared__ unsigned sBase;

    const int tid = threadIdx.x;
    const int gt  = blockIdx.x * NTHR + tid;

    if (tid == 0) sBase = atomicAdd(&g_barGen, 0u);    // frozen until all arrive

    // re-init state every launch (determinism across graph replays)
    for (int i = gt; i < BD; i += NCTA * NTHR) {
        const int d = i & (DIM - 1);
        g_h [i] = h0[d];  g_c [i] = c0[d];
        g_h2[i] = h02[d]; g_c2[i] = c02[d];
    }
    if (gt < 4 * DIM) g_bias[gt] = bih[gt] + bhh[gt];
    __syncthreads();
    const unsigned base = sBase;
    unsigned bc = 0;
    gridbar(base + ++bc);

    for (int t = 0; t < SEQL; t++) {
        const int* xt = x + t * BATCH;
        gemm_phase<1>(As, Ws, Abase, xt, emb, Wih, Whh);
        gridbar(base + ++bc);
        epi_phase<1>(xt);
        gridbar(base + ++bc);
        gemm_phase<2>(As, Ws, Abase, xt, emb, Wih, Whh);
        gridbar(base + ++bc);
        epi_phase<2>(xt);
        gridbar(base + ++bc);
    }

    for (int i = gt; i < BD; i += NCTA * NTHR) {
        out[i]          = g_h [i];
        out[BD + i]     = g_c [i];
        out[2 * BD + i] = g_h2[i];
        out[3 * BD + i] = g_c2[i];
    }
}

extern "C" void kernel_launch(void* const* d_in, const int* in_sizes, int n_in,
                              void* d_out, int out_size)
{
    (void)in_sizes; (void)n_in; (void)out_size;
    const int*   x   = (const int*)  d_in[0];   // [512, 128]
    const float* emb = (const float*)d_in[1];   // [32000, 1024]
    const float* Wih = (const float*)d_in[2];   // [4096, 1024]
    const float* Whh = (const float*)d_in[3];   // [4096, 1024]
    const float* bih = (const float*)d_in[4];   // [4096]
    const float* bhh = (const float*)d_in[5];   // [4096]
    const float* h0  = (const float*)d_in[6];   // [1024]
    const float* c0  = (const float*)d_in[7];
    const float* h02 = (const float*)d_in[8];
    const float* c02 = (const float*)d_in[9];

    const int smem = (2 * 128 * LDS_S + 2 * 256 * LDS_S) * 4 + 128 * 8;  // 111,616 B
    cudaFuncSetAttribute(lstm_persist, cudaFuncAttributeMaxDynamicSharedMemorySize, smem);

    lstm_persist<<<NCTA, NTHR, smem>>>(x, emb, Wih, Whh, bih, bhh,
                                       h0, c0, h02, c02, (float*)d_out);
}

// round 16
// speedup vs baseline: 1.0997x; 1.0997x over previous
#include <cuda_runtime.h>
#include <cstdint>

// SimplifiedEncoder: 2-layer weight-shared LSTM, SEQ=512, B=128, D=1024.
// ONE persistent kernel. Per cell: C[128x4096] = A[128x2048] @ Wcat^T,
// split across 128 CTAs = 16 n_tiles x 8 k_splits. tf32 mma.sync m16n8k8.
// R13 changes vs R12 (issue/latency-bound fix):
//   - all GEMM operands pre-converted to tf32 bits (no cvt in inner loop)
//   - 512 threads (16 warps, warp tile 64x32) for 2x latency hiding
//   - 3-stage cp.async pipeline, single __syncthreads per stage

#define BATCH  128
#define DIM    1024
#define BD     (BATCH * DIM)
#define SEQL   512
#define NCTA   128
#define NTHR   512
#define KC     32
#define NSTG   8          // 256 K per split / KC
#define LDS_S  36         // smem row stride (u32): (36r+c)%32 = (4r+c)%32 -> conflict-free
#define VOCAB  32000

// ---- persistent fp32 state ----
__device__ float g_h [BD];
__device__ float g_c [BD];
__device__ float g_h2[BD];
__device__ float g_c2[BD];
__device__ float g_h1[BD];
__device__ float g_c1[BD];
__device__ float g_bias[4 * DIM];
__device__ float g_P[8][BATCH][4 * DIM];       // split-K partials (16 MB)
// ---- tf32-bit operand mirrors ----
__device__ uint32_t g_ht  [BD];
__device__ uint32_t g_h2t [BD];
__device__ uint32_t g_h1t [BD];
__device__ uint32_t g_embt[(size_t)VOCAB * DIM];   // 131 MB
__device__ uint32_t g_Wiht[(size_t)4 * DIM * DIM]; // 16.8 MB
__device__ uint32_t g_Whht[(size_t)4 * DIM * DIM];
__device__ unsigned g_barGen = 0;              // monotonic across replays
__device__ unsigned g_barCnt = 0;

// ---- helpers ----
__device__ __forceinline__ void cp16(uint32_t* sdst, const uint32_t* gsrc) {
    unsigned s = (unsigned)__cvta_generic_to_shared(sdst);
    asm volatile("cp.async.cg.shared.global [%0], [%1], 16;\n" :: "r"(s), "l"(gsrc));
}
__device__ __forceinline__ void cp_commit() { asm volatile("cp.async.commit_group;\n"); }
__device__ __forceinline__ void cp_wait1()  { asm volatile("cp.async.wait_group 1;\n" ::: "memory"); }
__device__ __forceinline__ void cp_wait0()  { asm volatile("cp.async.wait_group 0;\n" ::: "memory"); }

__device__ __forceinline__ uint32_t tf32r(float v) {
    uint32_t r; asm("cvt.rna.tf32.f32 %0, %1;" : "=r"(r) : "f"(v)); return r;
}
__device__ __forceinline__ void mma8(float* d, const uint32_t* a, uint32_t b0, uint32_t b1) {
    asm volatile(
        "mma.sync.aligned.m16n8k8.row.col.f32.tf32.tf32.f32 "
        "{%0,%1,%2,%3}, {%4,%5,%6,%7}, {%8,%9}, {%0,%1,%2,%3};\n"
        : "+f"(d[0]), "+f"(d[1]), "+f"(d[2]), "+f"(d[3])
        : "r"(a[0]), "r"(a[1]), "r"(a[2]), "r"(a[3]), "r"(b0), "r"(b1));
}
__device__ __forceinline__ float sigf(float x)   { return __fdividef(1.0f, 1.0f + __expf(-x)); }
__device__ __forceinline__ float tanh_f(float x) { return __fmaf_rn(2.0f, sigf(2.0f * x), -1.0f); }

// Grid barrier, replay-safe monotonic generation.
__device__ __forceinline__ void gridbar(unsigned target) {
    __syncthreads();
    if (threadIdx.x == 0) {
        __threadfence();
        if (atomicAdd(&g_barCnt, 1u) == NCTA - 1u) {
            g_barCnt = 0u;
            __threadfence();
            atomicExch(&g_barGen, target);
        } else {
            while ((int)(*(volatile unsigned*)&g_barGen) - (int)target < 0) { }
        }
        __threadfence();
    }
    __syncthreads();
}

// ---- GEMM phase: partial [128 x 256] over a 256-wide K slice ----
// splits 0-3: first A-half (emb|h1) with Wih; 4-7: second half (h|h2) with Whh.
template<int LAYER>
__device__ void gemm_phase(uint32_t* As, uint32_t* Ws, const uint32_t** Abase,
                           const int* __restrict__ xt)
{
    const int tid = threadIdx.x;
    const int nt  = blockIdx.x & 15;
    const int ks  = blockIdx.x >> 4;
    const int n0  = nt * 256;
    const bool hi = (ks >= 4);
    const int koff = (ks & 3) * 256;

    if (tid < BATCH) {
        const uint32_t* b;
        if (LAYER == 1) b = hi ? (g_ht   + tid * DIM + koff)
                               : (g_embt + (size_t)xt[tid] * DIM + koff);
        else            b = hi ? (g_h2t  + tid * DIM + koff)
                               : (g_h1t  + tid * DIM + koff);
        Abase[tid] = b;
    }
    const uint32_t* Wb0 = (hi ? g_Whht : g_Wiht) + (size_t)n0 * DIM + koff;
    __syncthreads();

    float acc[4][4][4];
    #pragma unroll
    for (int qm = 0; qm < 4; qm++)
        #pragma unroll
        for (int qn = 0; qn < 4; qn++)
            #pragma unroll
            for (int p = 0; p < 4; p++) acc[qm][qn][p] = 0.0f;

    auto prefetch = [&](int s) {
        uint32_t* ad = As + (s % 3) * (128 * LDS_S);
        uint32_t* wd = Ws + (s % 3) * (256 * LDS_S);
        const int kc = s * KC;
        #pragma unroll
        for (int i = 0; i < 2; i++) {                 // A: 1024 16B chunks
            int cc = tid + i * NTHR;
            int r = cc >> 3, col = (cc & 7) * 4;
            cp16(ad + r * LDS_S + col, Abase[r] + kc + col);
        }
        #pragma unroll
        for (int i = 0; i < 4; i++) {                 // W: 2048 chunks
            int cc = tid + i * NTHR;
            int r = cc >> 3, col = (cc & 7) * 4;
            cp16(wd + r * LDS_S + col, Wb0 + (size_t)r * DIM + kc + col);
        }
        cp_commit();
    };

    const int lane = tid & 31, warp = tid >> 5;
    const int grp  = lane >> 2, tig = lane & 3;
    const int mb   = (warp >> 3) * 64;   // 2 warps in M
    const int nb   = (warp & 7) * 32;    // 8 warps in N

    auto docompute = [&](int s) {
        const uint32_t* Ab  = As + (s % 3) * (128 * LDS_S);
        const uint32_t* Wsb = Ws + (s % 3) * (256 * LDS_S);
        #pragma unroll
        for (int k8 = 0; k8 < KC / 8; k8++) {
            const int kk = k8 * 8;
            uint32_t af[4][4];
            #pragma unroll
            for (int qm = 0; qm < 4; qm++) {
                const uint32_t* p = Ab + (mb + qm * 16 + grp) * LDS_S + kk + tig;
                af[qm][0] = p[0];
                af[qm][1] = p[8 * LDS_S];
                af[qm][2] = p[4];
                af[qm][3] = p[8 * LDS_S + 4];
            }
            uint32_t bf[4][2];
            #pragma unroll
            for (int qn = 0; qn < 4; qn++) {
                const uint32_t* p = Wsb + (nb + qn * 8 + grp) * LDS_S + kk + tig;
                bf[qn][0] = p[0];
                bf[qn][1] = p[4];
            }
            #pragma unroll
            for (int qm = 0; qm < 4; qm++)
                #pragma unroll
                for (int qn = 0; qn < 4; qn++)
                    mma8(acc[qm][qn], af[qm], bf[qn][0], bf[qn][1]);
        }
    };

    prefetch(0);
    prefetch(1);
    #pragma unroll 1
    for (int s = 0; s < NSTG; s++) {
        if (s == NSTG - 1) cp_wait0(); else cp_wait1();
        __syncthreads();                    // buf s visible; compute(s-1) drained
        if (s + 2 < NSTG) prefetch(s + 2);  // writes buf (s+2)%3, free since sync
        docompute(s);
    }

    float* Pks = &g_P[ks][0][0];
    #pragma unroll
    for (int qm = 0; qm < 4; qm++) {
        #pragma unroll
        for (int qn = 0; qn < 4; qn++) {
            const int b0  = mb + qm * 16 + grp;
            const int col = n0 + nb + qn * 8 + 2 * tig;
            *(float2*)(Pks + (size_t)b0 * 4096 + col) =
                make_float2(acc[qm][qn][0], acc[qm][qn][1]);
            *(float2*)(Pks + (size_t)(b0 + 8) * 4096 + col) =
                make_float2(acc[qm][qn][2], acc[qm][qn][3]);
        }
    }
}

// ---- reduction + LSTM epilogue. CTA = batch row; threads sweep j. ----
template<int LAYER>
__device__ void epi_phase(const int* __restrict__ xt)
{
    const int b = blockIdx.x;
    const bool pad = (xt[b] == 0);
    #pragma unroll
    for (int q = 0; q < DIM / NTHR; q++) {
        const int j = q * NTHR + threadIdx.x;
        float s[4];
        #pragma unroll
        for (int g = 0; g < 4; g++) {
            float a = g_bias[g * DIM + j];
            #pragma unroll
            for (int sp = 0; sp < 8; sp++)
                a += g_P[sp][b][g * DIM + j];
            s[g] = a;
        }
        const int idx = b * DIM + j;
        const float ig = sigf(s[0]);
        const float fg = sigf(s[1]);
        const float gg = tanh_f(s[2]);
        const float og = sigf(s[3]);
        if (LAYER == 1) {
            const float cn = fg * g_c[idx] + ig * gg;
            const float hn = og * tanh_f(cn);
            g_c1[idx]  = cn;
            g_h1[idx]  = hn;
            g_h1t[idx] = tf32r(hn);
        } else {
            const float c2n = fg * g_c2[idx] + ig * gg;
            const float h2n = og * tanh_f(c2n);
            const float hold = g_h[idx];
            const float cold = g_c[idx];
            // faithful to reference: layer-2 pads fall back to layer-1 PRE-step state
            const float hN  = pad ? hold : g_h1[idx];
            const float cN  = pad ? cold : g_c1[idx];
            const float h2N = pad ? hold : h2n;
            const float c2N = pad ? cold : c2n;
            g_h [idx] = hN;   g_ht [idx] = tf32r(hN);
            g_c [idx] = cN;
            g_h2[idx] = h2N;  g_h2t[idx] = tf32r(h2N);
            g_c2[idx] = c2N;
        }
    }
}

// ---- single persistent kernel ----
__global__ void __launch_bounds__(NTHR, 1)
lstm_persist(const int*   __restrict__ x,
             const float* __restrict__ emb,
             const float* __restrict__ Wih,
             const float* __restrict__ Whh,
             const float* __restrict__ bih,
             const float* __restrict__ bhh,
             const float* __restrict__ h0,
             const float* __restrict__ c0,
             const float* __restrict__ h02,
             const float* __restrict__ c02,
             float* __restrict__ out)
{
    extern __shared__ uint32_t smu[];
    uint32_t* As = smu;                                 // [3][128*36]
    uint32_t* Ws = smu + 3 * 128 * LDS_S;               // [3][256*36]
    const uint32_t** Abase =
        (const uint32_t**)(smu + 3 * 128 * LDS_S + 3 * 256 * LDS_S);
    __shared__ unsigned sBase;

    const int tid = threadIdx.x;
    const int gt  = blockIdx.x * NTHR + tid;
    const int GT  = NCTA * NTHR;                        // 65536 threads

    if (tid == 0) sBase = atomicAdd(&g_barGen, 0u);

    // per-launch init (determinism across graph replays)
    for (int i = gt; i < BD; i += GT) {
        const int d = i & (DIM - 1);
        const float hv = h0[d], h2v = h02[d];
        g_h [i] = hv;   g_ht [i] = tf32r(hv);
        g_c [i] = c0[d];
        g_h2[i] = h2v;  g_h2t[i] = tf32r(h2v);
        g_c2[i] = c02[d];
    }
    if (gt < 4 * DIM) g_bias[gt] = bih[gt] + bhh[gt];
    // pre-convert weights + embedding to tf32 bits (vectorized)
    {
        const float4* e4 = (const float4*)emb;
        uint4* d4 = (uint4*)g_embt;
        const int N4 = VOCAB * DIM / 4;
        for (int i = gt; i < N4; i += GT) {
            float4 v = e4[i];
            d4[i] = make_uint4(tf32r(v.x), tf32r(v.y), tf32r(v.z), tf32r(v.w));
        }
        const int W4 = 4 * DIM * DIM / 4;
        const float4* a4 = (const float4*)Wih;
        const float4* b4 = (const float4*)Whh;
        uint4* ad = (uint4*)g_Wiht;
        uint4* bd = (uint4*)g_Whht;
        for (int i = gt; i < W4; i += GT) {
            float4 v = a4[i];
            ad[i] = make_uint4(tf32r(v.x), tf32r(v.y), tf32r(v.z), tf32r(v.w));
            float4 w = b4[i];
            bd[i] = make_uint4(tf32r(w.x), tf32r(w.y), tf32r(w.z), tf32r(w.w));
        }
    }
    __syncthreads();
    const unsigned base = sBase;
    unsigned bc = 0;
    gridbar(base + ++bc);

    for (int t = 0; t < SEQL; t++) {
        const int* xt = x + t * BATCH;
        gemm_phase<1>(As, Ws, Abase, xt);
        gridbar(base + ++bc);
        epi_phase<1>(xt);
        gridbar(base + ++bc);
        gemm_phase<2>(As, Ws, Abase, xt);
        gridbar(base + ++bc);
        epi_phase<2>(xt);
        gridbar(base + ++bc);
    }

    for (int i = gt; i < BD; i += GT) {
        out[i]          = g_h [i];
        out[BD + i]     = g_c [i];
        out[2 * BD + i] = g_h2[i];
        out[3 * BD + i] = g_c2[i];
    }
}

extern "C" void kernel_launch(void* const* d_in, const int* in_sizes, int n_in,
                              void* d_out, int out_size)
{
    (void)in_sizes; (void)n_in; (void)out_size;
    const int*   x   = (const int*)  d_in[0];
    const float* emb = (const float*)d_in[1];
    const float* Wih = (const float*)d_in[2];
    const float* Whh = (const float*)d_in[3];
    const float* bih = (const float*)d_in[4];
    const float* bhh = (const float*)d_in[5];
    const float* h0  = (const float*)d_in[6];
    const float* c0  = (const float*)d_in[7];
    const float* h02 = (const float*)d_in[8];
    const float* c02 = (const float*)d_in[9];

    const int smem = (3 * 128 * LDS_S + 3 * 256 * LDS_S) * 4 + 128 * 8;  // 166,912 B
    cudaFuncSetAttribute(lstm_persist, cudaFuncAttributeMaxDynamicSharedMemorySize, smem);

    lstm_persist<<<NCTA, NTHR, smem>>>(x, emb, Wih, Whh, bih, bhh,
                                       h0, c0, h02, c02, (float*)d_out);
}